// round 7
// baseline (speedup 1.0000x reference)
#include <cuda_runtime.h>
#include <cuda_bf16.h>

typedef unsigned long long u64;

#define F_E   10
#define F_XT  5
#define F_XS  10
#define F_U   10
#define D1    15
#define D2    81
#define MAXN  100000
#define MAXE  4000000
#define MAXPAD (MAXE + 4 * MAXN)

// ---- device scratch (no allocs allowed) ------------------------------------
__device__ int g_hist[MAXN];
__device__ int g_start[MAXN];
__device__ int g_cursor[MAXN];
__device__ int g_end[MAXN];
__device__ int g_totalpad;
__device__ __align__(16) float g_recs[(size_t)MAXPAD * 16];   // 64B records
__device__ __align__(16) float g_acc[(size_t)MAXN * 64];      // cnt,S1,S2,S3,S4

// ---- f32x2 packed helpers ----------------------------------------------------
__device__ __forceinline__ u64 pk(float a, float b) {
    u64 r; asm("mov.b64 %0, {%1, %2};" : "=l"(r) : "f"(a), "f"(b)); return r;
}
__device__ __forceinline__ void upk(u64 v, float& a, float& b) {
    asm("mov.b64 {%0, %1}, %2;" : "=f"(a), "=f"(b) : "l"(v));
}
__device__ __forceinline__ u64 fma2(u64 a, u64 b, u64 c) {
    u64 d; asm("fma.rn.f32x2 %0, %1, %2, %3;" : "=l"(d) : "l"(a), "l"(b), "l"(c)); return d;
}
__device__ __forceinline__ u64 mul2(u64 a, u64 b) {
    u64 d; asm("mul.rn.f32x2 %0, %1, %2;" : "=l"(d) : "l"(a), "l"(b)); return d;
}
__device__ __forceinline__ u64 add2(u64 a, u64 b) {
    u64 d; asm("add.rn.f32x2 %0, %1, %2;" : "=l"(d) : "l"(a), "l"(b)); return d;
}
__device__ __forceinline__ float hsum2(u64 v) {
    float a, b; upk(v, a, b); return a + b;
}

// ---- 1: zero hist + acc --------------------------------------------------------
__global__ void zero_kernel(int n) {   // n = nS
    int stride = gridDim.x * blockDim.x;
    int i = blockIdx.x * blockDim.x + threadIdx.x;
    for (int k = i; k < n; k += stride) g_hist[k] = 0;
    int total4 = n * 16;
    for (int k = i; k < total4; k += stride)
        reinterpret_cast<float4*>(g_acc)[k] = make_float4(0.f, 0.f, 0.f, 0.f);
}

// ---- 2: histogram ---------------------------------------------------------------
__global__ void hist_kernel(const int* __restrict__ src, int E_) {
    long long base = ((long long)blockIdx.x * blockDim.x + threadIdx.x) * 4;
    if (base >= E_) return;
    if (base + 4 <= E_) {
        int4 s = *(const int4*)(src + base);
        atomicAdd(&g_hist[s.x], 1);
        atomicAdd(&g_hist[s.y], 1);
        atomicAdd(&g_hist[s.z], 1);
        atomicAdd(&g_hist[s.w], 1);
    } else {
        for (long long e = base; e < E_; e++) atomicAdd(&g_hist[src[e]], 1);
    }
}

// ---- 3: single-block scan over padded counts -----------------------------------
__global__ void scan_kernel(int n) {   // <<<1, 1024>>>
    __shared__ int ssum[1024];
    int tid = threadIdx.x;
    int per = (n + 1023) / 1024;
    int lo = tid * per;
    int hi = (lo + per < n) ? lo + per : n;
    int sum = 0;
    for (int i = lo; i < hi; i++) sum += (g_hist[i] + 3) & ~3;
    ssum[tid] = sum;
    __syncthreads();
#pragma unroll
    for (int off = 1; off < 1024; off <<= 1) {
        int t = (tid >= off) ? ssum[tid - off] : 0;
        __syncthreads();
        ssum[tid] += t;
        __syncthreads();
    }
    int run = ssum[tid] - sum;      // exclusive prefix
    for (int i = lo; i < hi; i++) {
        int c = g_hist[i];
        g_start[i] = run;
        g_cursor[i] = run;
        g_end[i] = run + c;
        run += (c + 3) & ~3;
    }
    if (tid == 1023) g_totalpad = ssum[1023];
}

// ---- 4: scatter records into sorted+padded slots -------------------------------
// record (16 floats): [0..4]=x_t[tgt], [5..14]=edge_attr, [15]=int_bits(src+1) (0 for pads)
__global__ __launch_bounds__(256) void scatter_kernel(
    const int* __restrict__ eidx,
    const float* __restrict__ x_t,
    const float* __restrict__ edge_attr,
    int E_)
{
    long long base = ((long long)blockIdx.x * blockDim.x + threadIdx.x) * 4;
    if (base >= E_) return;
    int ecnt = (int)(((long long)E_ - base) < 4 ? ((long long)E_ - base) : 4);

    int srcs[4], tgs[4];
    float fl[40];
    if (ecnt == 4) {
        int4 s4 = *(const int4*)(eidx + base);
        int4 g4 = *(const int4*)(eidx + (size_t)E_ + base);
        srcs[0] = s4.x; srcs[1] = s4.y; srcs[2] = s4.z; srcs[3] = s4.w;
        tgs[0] = g4.x; tgs[1] = g4.y; tgs[2] = g4.z; tgs[3] = g4.w;
        const float4* ea = (const float4*)(edge_attr + base * F_E);
#pragma unroll
        for (int r = 0; r < 10; r++) {
            float4 q = __ldg(ea + r);
            fl[4 * r + 0] = q.x; fl[4 * r + 1] = q.y;
            fl[4 * r + 2] = q.z; fl[4 * r + 3] = q.w;
        }
    } else {
#pragma unroll
        for (int k = 0; k < 4; k++) {
            long long e = (k < ecnt) ? base + k : base;
            srcs[k] = eidx[e];
            tgs[k] = eidx[(size_t)E_ + e];
#pragma unroll
            for (int c = 0; c < F_E; c++)
                fl[10 * k + c] = edge_attr[e * F_E + c];
        }
    }

#pragma unroll
    for (int k = 0; k < 4; k++) {
        if (k >= ecnt) break;
        int src = srcs[k], tgt = tgs[k];
        int pos = atomicAdd(&g_cursor[src], 1);
        const float* xp = x_t + (size_t)tgt * F_XT;
        float x0 = __ldg(xp), x1 = __ldg(xp + 1), x2 = __ldg(xp + 2),
              x3 = __ldg(xp + 3), x4 = __ldg(xp + 4);
        const float* a = fl + 10 * k;
        float4* r = (float4*)(g_recs + (size_t)pos * 16);
        r[0] = make_float4(x0, x1, x2, x3);
        r[1] = make_float4(x4, a[0], a[1], a[2]);
        r[2] = make_float4(a[3], a[4], a[5], a[6]);
        r[3] = make_float4(a[7], a[8], a[9], __int_as_float(src + 1));

        // the thread that fills the node's last real slot writes the pads
        int end = g_end[src];
        if (pos == end - 1) {
            int st = g_start[src];
            int pe = st + (((end - st) + 3) & ~3);
            float4 z = make_float4(0.f, 0.f, 0.f, 0.f);
            for (int q = end; q < pe; q++) {
                float4* pr = (float4*)(g_recs + (size_t)q * 16);
                pr[0] = z; pr[1] = z; pr[2] = z; pr[3] = z;
            }
        }
    }
}

// ---- 5: MLP over sorted chunks, reduce in-register, RED flush -------------------
__global__ __launch_bounds__(128) void mlp_kernel(
    const float* __restrict__ w1a, const float* __restrict__ b1a,
    const float* __restrict__ w2a, const float* __restrict__ b2a)
{
    __shared__ float2 sw1[D1 * D1];
    __shared__ float2 sw2[D1 * D1];
    __shared__ float2 sb1[D1];
    __shared__ float2 sb2[D1];
    for (int i = threadIdx.x; i < D1 * D1; i += blockDim.x) {
        float w = w1a[i]; sw1[i] = make_float2(w, w);
        w = w2a[i];       sw2[i] = make_float2(w, w);
    }
    if (threadIdx.x < D1) {
        float v = b1a[threadIdx.x]; sb1[threadIdx.x] = make_float2(v, v);
        v = b2a[threadIdx.x];       sb2[threadIdx.x] = make_float2(v, v);
    }
    __syncthreads();

    long long t = (long long)blockIdx.x * blockDim.x + threadIdx.x;
    long long base = t * 4;                 // record index
    if (base >= g_totalpad) return;

    // 4 records = 16 float4, contiguous 256B
    float4 r[16];
    {
        const float4* R = (const float4*)(g_recs + base * 16);
#pragma unroll
        for (int i = 0; i < 16; i++) r[i] = R[i];
    }
    int src = __float_as_int(r[3].w) - 1;   // record 0 is always real
    float w0 = 1.f;
    float w1 = (__float_as_int(r[7].w)  != 0) ? 1.f : 0.f;
    float w2 = (__float_as_int(r[11].w) != 0) ? 1.f : 0.f;
    float w3 = (__float_as_int(r[15].w) != 0) ? 1.f : 0.f;

    // unpack 15 inputs per record, pack pairs {0,1} -> v0, {2,3} -> v1
    u64 v0[D1], v1[D1];
    {
        float e0[D1], e1[D1], e2[D1], e3[D1];
#define EXTR(dst, o) \
        dst[0]=r[o].x; dst[1]=r[o].y; dst[2]=r[o].z; dst[3]=r[o].w; \
        dst[4]=r[o+1].x; dst[5]=r[o+1].y; dst[6]=r[o+1].z; dst[7]=r[o+1].w; \
        dst[8]=r[o+2].x; dst[9]=r[o+2].y; dst[10]=r[o+2].z; dst[11]=r[o+2].w; \
        dst[12]=r[o+3].x; dst[13]=r[o+3].y; dst[14]=r[o+3].z;
        EXTR(e0, 0) EXTR(e1, 4) EXTR(e2, 8) EXTR(e3, 12)
#undef EXTR
#pragma unroll
        for (int i = 0; i < D1; i++) {
            v0[i] = pk(e0[i], e1[i]);
            v1[i] = pk(e2[i], e3[i]);
        }
    }

    const u64* W1 = (const u64*)sw1;
    const u64* W2 = (const u64*)sw2;
    const u64* B1 = (const u64*)sb1;
    const u64* B2 = (const u64*)sb2;

    u64 h0[D1], h1[D1];
#pragma unroll
    for (int j = 0; j < D1; j++) {
        u64 s0 = B1[j], s1 = s0;
#pragma unroll
        for (int i = 0; i < D1; i++) {
            u64 w = W1[i * D1 + j];
            s0 = fma2(v0[i], w, s0);
            s1 = fma2(v1[i], w, s1);
        }
        float a, b;
        upk(s0, a, b); a = fmaxf(a, 0.1f * a); b = fmaxf(b, 0.1f * b); h0[j] = pk(a, b);
        upk(s1, a, b); a = fmaxf(a, 0.1f * a); b = fmaxf(b, 0.1f * b); h1[j] = pk(a, b);
    }

    // layer 2 overwrites v0/v1
#pragma unroll
    for (int j = 0; j < D1; j++) {
        u64 s0 = B2[j], s1 = s0;
#pragma unroll
        for (int i = 0; i < D1; i++) {
            u64 w = W2[i * D1 + j];
            s0 = fma2(h0[i], w, s0);
            s1 = fma2(h1[i], w, s1);
        }
        v0[j] = s0; v1[j] = s1;
    }

    // mask pads, packed powers, horizontal sums
    u64 wm0 = pk(w0, w1), wm1 = pk(w2, w3);
    float S1[D1], S2[D1], S3[D1], S4[D1];
#pragma unroll
    for (int j = 0; j < D1; j++) {
        u64 a = mul2(v0[j], wm0);
        u64 b = mul2(v1[j], wm1);
        u64 a2 = mul2(a, a),   b2 = mul2(b, b);
        u64 a3 = mul2(a2, a),  b3 = mul2(b2, b);
        u64 a4 = mul2(a2, a2), b4 = mul2(b2, b2);
        S1[j] = hsum2(add2(a, b));
        S2[j] = hsum2(add2(a2, b2));
        S3[j] = hsum2(add2(a3, b3));
        S4[j] = hsum2(add2(a4, b4));
    }
    float cnt = hsum2(add2(wm0, wm1));

    float4* basep = (float4*)(g_acc + (size_t)src * 64);
#define VAL(idx) \
    ((idx) == 0 ? cnt : \
     (idx) <= 15 ? S1[(idx) - 1] : \
     (idx) <= 30 ? S2[(idx) - 16] : \
     (idx) <= 45 ? S3[(idx) - 31] : \
     (idx) <= 60 ? S4[(idx) - 46] : 0.f)
#pragma unroll
    for (int q = 0; q < 16; q++) {
        float4 v;
        v.x = VAL(4 * q + 0);
        v.y = VAL(4 * q + 1);
        v.z = VAL(4 * q + 2);
        v.w = VAL(4 * q + 3);
        atomicAdd(basep + q, v);
    }
#undef VAL
}

// ---- 6: node kernel: stats from raw moments + 81->10->10 MLP --------------------
__global__ __launch_bounds__(256) void node_kernel(
    const float* __restrict__ x_s,
    const float* __restrict__ u,
    const int* __restrict__ batch_s,
    const float* __restrict__ w1b, const float* __restrict__ b1b,
    const float* __restrict__ w2b, const float* __restrict__ b2b,
    float* __restrict__ out, int n)
{
    __shared__ float sw1[D2 * F_XS];
    __shared__ float sw2[F_XS * F_XS];
    __shared__ float sb1[F_XS];
    __shared__ float sb2[F_XS];
    for (int i = threadIdx.x; i < D2 * F_XS; i += blockDim.x) sw1[i] = w1b[i];
    for (int i = threadIdx.x; i < F_XS * F_XS; i += blockDim.x) sw2[i] = w2b[i];
    if (threadIdx.x < F_XS) {
        sb1[threadIdx.x] = b1b[threadIdx.x];
        sb2[threadIdx.x] = b2b[threadIdx.x];
    }
    __syncthreads();

    int nid = blockIdx.x * blockDim.x + threadIdx.x;
    if (nid >= n) return;

    const float* acc = g_acc + (size_t)nid * 64;

    float t[F_XS];
#pragma unroll
    for (int j = 0; j < F_XS; j++) t[j] = sb1[j];

#define ADD_FEAT(fv, i) do { \
        float _f = (fv); \
_Pragma("unroll") \
        for (int _j = 0; _j < F_XS; _j++) \
            t[_j] = fmaf(_f, sw1[(i) * F_XS + _j], t[_j]); \
    } while (0)

#pragma unroll
    for (int k = 0; k < F_XS; k++) ADD_FEAT(x_s[(size_t)nid * F_XS + k], k);

    float cnt = acc[0];
    ADD_FEAT(cnt, 10);

    float denom = fmaxf(cnt, 1.f);
    float rin = 1.f / denom;

#pragma unroll
    for (int j = 0; j < D1; j++) {
        float s1 = acc[1 + j]  * rin;
        float s2 = acc[16 + j] * rin;
        float s3 = acc[31 + j] * rin;
        float s4 = acc[46 + j] * rin;
        float mu  = s1;
        float mu2 = mu * mu;
        float var = fmaxf(s2 - mu2, 0.f);
        float std_ = sqrtf(var + 1e-6f);
        float m3 = s3 - 3.f * mu * s2 + 2.f * mu * mu2;
        float m4 = s4 - 4.f * mu * s3 + 6.f * mu2 * s2 - 3.f * mu2 * mu2;
        float is  = 1.f / std_;
        float is2 = is * is;
        ADD_FEAT(mu,             11 + j);
        ADD_FEAT(std_,           26 + j);
        ADD_FEAT(m3 * is2 * is,  41 + j);
        ADD_FEAT(m4 * is2 * is2, 56 + j);
    }

    int b = batch_s[nid];
#pragma unroll
    for (int k = 0; k < F_U; k++) ADD_FEAT(u[(size_t)b * F_U + k], 71 + k);
#undef ADD_FEAT

    float a[F_XS];
#pragma unroll
    for (int j = 0; j < F_XS; j++) a[j] = (t[j] > 0.f) ? t[j] : 0.1f * t[j];

#pragma unroll
    for (int j = 0; j < F_XS; j++) {
        float s = sb2[j];
#pragma unroll
        for (int i = 0; i < F_XS; i++) s = fmaf(a[i], sw2[i * F_XS + j], s);
        out[(size_t)nid * F_XS + j] = s;
    }
}

// ---------------------------------------------------------------------------
extern "C" void kernel_launch(void* const* d_in, const int* in_sizes, int n_in,
                              void* d_out, int out_size)
{
    const float* x_s       = (const float*)d_in[0];
    const float* x_t       = (const float*)d_in[1];
    const float* edge_attr = (const float*)d_in[2];
    const float* u         = (const float*)d_in[3];
    const int*   eidx      = (const int*)d_in[4];
    const int*   batch_s   = (const int*)d_in[5];
    const float* w1a = (const float*)d_in[6];
    const float* b1a = (const float*)d_in[7];
    const float* w2a = (const float*)d_in[8];
    const float* b2a = (const float*)d_in[9];
    const float* w1b = (const float*)d_in[10];
    const float* b1b = (const float*)d_in[11];
    const float* w2b = (const float*)d_in[12];
    const float* b2b = (const float*)d_in[13];

    int nS = in_sizes[0] / F_XS;     // 100000
    int E_ = in_sizes[2] / F_E;      // 4000000
    float* out = (float*)d_out;

    long long boundPad = (long long)E_ + 3LL * nS + 8;   // >= totalpad
    long long mlpThreads = (boundPad + 3) / 4;

    zero_kernel<<<592, 256>>>(nS);
    hist_kernel<<<(E_ / 4 + 255) / 256 + 1, 256>>>(eidx, E_);
    scan_kernel<<<1, 1024>>>(nS);
    scatter_kernel<<<(E_ / 4 + 255) / 256 + 1, 256>>>(eidx, x_t, edge_attr, E_);
    mlp_kernel<<<(int)((mlpThreads + 127) / 128), 128>>>(w1a, b1a, w2a, b2a);
    node_kernel<<<(nS + 255) / 256, 256>>>(x_s, u, batch_s,
                                           w1b, b1b, w2b, b2b, out, nS);
}

// round 8
// speedup vs baseline: 2.3840x; 2.3840x over previous
#include <cuda_runtime.h>
#include <cuda_bf16.h>

typedef unsigned long long u64;

#define F_E   10
#define F_XT  5
#define F_XS  10
#define F_U   10
#define D1    15
#define D2    81
#define MAXN  100000
#define MAXE  4000000

// ---- device scratch (no allocs allowed) ------------------------------------
__device__ int g_hist[MAXN];
__device__ int g_start[MAXN];
__device__ int g_rank[MAXE];
__device__ int g_bsum[128];
__device__ __align__(16) float g_scratch[(size_t)MAXE * 16];   // 256MB msg rows
__device__ __align__(16) float g_stats[(size_t)MAXN * 64];     // {mu,std,skew,kurt} per (n,j)

// ---- f32x2 packed helpers ----------------------------------------------------
__device__ __forceinline__ u64 pk(float a, float b) {
    u64 r; asm("mov.b64 %0, {%1, %2};" : "=l"(r) : "f"(a), "f"(b)); return r;
}
__device__ __forceinline__ void upk(u64 v, float& a, float& b) {
    asm("mov.b64 {%0, %1}, %2;" : "=f"(a), "=f"(b) : "l"(v));
}
__device__ __forceinline__ u64 fma2(u64 a, u64 b, u64 c) {
    u64 d; asm("fma.rn.f32x2 %0, %1, %2, %3;" : "=l"(d) : "l"(a), "l"(b), "l"(c)); return d;
}

// ---- tiny kernels -------------------------------------------------------------
__global__ void zero_hist(int n) {
    int i = blockIdx.x * blockDim.x + threadIdx.x;
    if (i < n) g_hist[i] = 0;
}

// histogram + per-edge rank (old value of the atomic)
__global__ void hist_kernel(const int* __restrict__ src, int E_) {
    long long base = ((long long)blockIdx.x * blockDim.x + threadIdx.x) * 4;
    if (base >= E_) return;
    if (base + 4 <= E_) {
        int4 s = *(const int4*)(src + base);
        int r0 = atomicAdd(&g_hist[s.x], 1);
        int r1 = atomicAdd(&g_hist[s.y], 1);
        int r2 = atomicAdd(&g_hist[s.z], 1);
        int r3 = atomicAdd(&g_hist[s.w], 1);
        *(int4*)(g_rank + base) = make_int4(r0, r1, r2, r3);
    } else {
        for (long long e = base; e < E_; e++)
            g_rank[e] = atomicAdd(&g_hist[src[e]], 1);
    }
}

// block-wise exclusive scan (1024/block)
__global__ void scan1(int n) {
    __shared__ int s[1024];
    int gid = blockIdx.x * 1024 + threadIdx.x;
    int v = (gid < n) ? g_hist[gid] : 0;
    s[threadIdx.x] = v;
    __syncthreads();
#pragma unroll
    for (int off = 1; off < 1024; off <<= 1) {
        int t = (threadIdx.x >= off) ? s[threadIdx.x - off] : 0;
        __syncthreads();
        s[threadIdx.x] += t;
        __syncthreads();
    }
    int incl = s[threadIdx.x];
    if (gid < n) g_start[gid] = incl - v;
    if (threadIdx.x == 1023) g_bsum[blockIdx.x] = incl;
}

__global__ void scan2(int nb) {
    __shared__ int s[128];
    int v = (threadIdx.x < nb) ? g_bsum[threadIdx.x] : 0;
    s[threadIdx.x] = v;
    __syncthreads();
#pragma unroll
    for (int off = 1; off < 128; off <<= 1) {
        int t = (threadIdx.x >= off) ? s[threadIdx.x - off] : 0;
        __syncthreads();
        s[threadIdx.x] += t;
        __syncthreads();
    }
    if (threadIdx.x < nb) g_bsum[threadIdx.x] = s[threadIdx.x] - v;
}

__global__ void scan3(int n) {
    int gid = blockIdx.x * 1024 + threadIdx.x;
    if (gid < n) g_start[gid] += g_bsum[blockIdx.x];
}

// ---- edge kernel: 4 edges/thread, f32x2 MLP, streaming scattered writes -------
__global__ __launch_bounds__(128) void edge_kernel(
    const float* __restrict__ x_t,
    const float* __restrict__ edge_attr,
    const int* __restrict__ eidx,
    const float* __restrict__ w1a, const float* __restrict__ b1a,
    const float* __restrict__ w2a, const float* __restrict__ b2a,
    int E_)
{
    __shared__ float2 sw1[D1 * D1];
    __shared__ float2 sw2[D1 * D1];
    __shared__ float2 sb1[D1];
    __shared__ float2 sb2[D1];
    for (int i = threadIdx.x; i < D1 * D1; i += blockDim.x) {
        float w = w1a[i]; sw1[i] = make_float2(w, w);
        w = w2a[i];       sw2[i] = make_float2(w, w);
    }
    if (threadIdx.x < D1) {
        float v = b1a[threadIdx.x]; sb1[threadIdx.x] = make_float2(v, v);
        v = b2a[threadIdx.x];       sb2[threadIdx.x] = make_float2(v, v);
    }
    __syncthreads();

    long long t = (long long)blockIdx.x * blockDim.x + threadIdx.x;
    long long base = t * 4;
    if (base >= E_) return;
    int ecnt = (int)(((long long)E_ - base) < 4 ? ((long long)E_ - base) : 4);

    int srcs[4], tgs[4], rks[4];
    if (ecnt == 4) {
        int4 s4 = *(const int4*)(eidx + base);
        int4 g4 = *(const int4*)(eidx + (size_t)E_ + base);
        int4 r4 = *(const int4*)(g_rank + base);
        srcs[0] = s4.x; srcs[1] = s4.y; srcs[2] = s4.z; srcs[3] = s4.w;
        tgs[0] = g4.x; tgs[1] = g4.y; tgs[2] = g4.z; tgs[3] = g4.w;
        rks[0] = r4.x; rks[1] = r4.y; rks[2] = r4.z; rks[3] = r4.w;
    } else {
#pragma unroll
        for (int k = 0; k < 4; k++) {
            long long e = (k < ecnt) ? base + k : base;
            srcs[k] = eidx[e];
            tgs[k] = eidx[(size_t)E_ + e];
            rks[k] = g_rank[e];
        }
    }

    // deterministic sorted slots (no atomics)
    int pos[4];
#pragma unroll
    for (int k = 0; k < 4; k++) pos[k] = g_start[srcs[k]] + rks[k];

    // v0 = packed inputs for edges {0,1}, v1 = {2,3}; reused as layer-2 outputs
    u64 v0[D1], v1[D1];
#pragma unroll
    for (int c = 0; c < F_XT; c++) {
        v0[c] = pk(__ldg(x_t + (size_t)tgs[0] * F_XT + c),
                   __ldg(x_t + (size_t)tgs[1] * F_XT + c));
        v1[c] = pk(__ldg(x_t + (size_t)tgs[2] * F_XT + c),
                   __ldg(x_t + (size_t)tgs[3] * F_XT + c));
    }
    if (ecnt == 4) {
        float fl[40];
        const float4* ea = (const float4*)(edge_attr + base * F_E);
#pragma unroll
        for (int r = 0; r < 10; r++) {
            float4 q = __ldcs(ea + r);      // streaming: single use
            fl[4 * r + 0] = q.x; fl[4 * r + 1] = q.y;
            fl[4 * r + 2] = q.z; fl[4 * r + 3] = q.w;
        }
#pragma unroll
        for (int c = 0; c < F_E; c++) {
            v0[F_XT + c] = pk(fl[c], fl[10 + c]);
            v1[F_XT + c] = pk(fl[20 + c], fl[30 + c]);
        }
    } else {
#pragma unroll
        for (int c = 0; c < F_E; c++) {
            long long e0 = base, e1 = (1 < ecnt) ? base + 1 : base;
            long long e2 = (2 < ecnt) ? base + 2 : base, e3 = (3 < ecnt) ? base + 3 : base;
            v0[F_XT + c] = pk(edge_attr[e0 * F_E + c], edge_attr[e1 * F_E + c]);
            v1[F_XT + c] = pk(edge_attr[e2 * F_E + c], edge_attr[e3 * F_E + c]);
        }
    }

    const u64* W1 = (const u64*)sw1;
    const u64* W2 = (const u64*)sw2;
    const u64* B1 = (const u64*)sb1;
    const u64* B2 = (const u64*)sb2;

    u64 h0[D1], h1[D1];
#pragma unroll
    for (int j = 0; j < D1; j++) {
        u64 s0 = B1[j], s1 = s0;
#pragma unroll
        for (int i = 0; i < D1; i++) {
            u64 w = W1[i * D1 + j];
            s0 = fma2(v0[i], w, s0);
            s1 = fma2(v1[i], w, s1);
        }
        float a, b;
        upk(s0, a, b); a = fmaxf(a, 0.1f * a); b = fmaxf(b, 0.1f * b); h0[j] = pk(a, b);
        upk(s1, a, b); a = fmaxf(a, 0.1f * a); b = fmaxf(b, 0.1f * b); h1[j] = pk(a, b);
    }

    // layer 2 overwrites v0/v1 (inputs fully consumed)
#pragma unroll
    for (int j = 0; j < D1; j++) {
        u64 s0 = B2[j], s1 = s0;
#pragma unroll
        for (int i = 0; i < D1; i++) {
            u64 w = W2[i * D1 + j];
            s0 = fma2(h0[i], w, s0);
            s1 = fma2(h1[i], w, s1);
        }
        v0[j] = s0; v1[j] = s1;
    }

    // write 64B sorted rows (streaming stores, evict-first)
    {
        float a[D1], b[D1];
#pragma unroll
        for (int j = 0; j < D1; j++) upk(v0[j], a[j], b[j]);
        float4* r = (float4*)(g_scratch + (size_t)pos[0] * 16);
        if (0 < ecnt) {
            __stcs(r + 0, make_float4(a[0], a[1], a[2], a[3]));
            __stcs(r + 1, make_float4(a[4], a[5], a[6], a[7]));
            __stcs(r + 2, make_float4(a[8], a[9], a[10], a[11]));
            __stcs(r + 3, make_float4(a[12], a[13], a[14], 0.f));
        }
        r = (float4*)(g_scratch + (size_t)pos[1] * 16);
        if (1 < ecnt) {
            __stcs(r + 0, make_float4(b[0], b[1], b[2], b[3]));
            __stcs(r + 1, make_float4(b[4], b[5], b[6], b[7]));
            __stcs(r + 2, make_float4(b[8], b[9], b[10], b[11]));
            __stcs(r + 3, make_float4(b[12], b[13], b[14], 0.f));
        }
    }
    {
        float a[D1], b[D1];
#pragma unroll
        for (int j = 0; j < D1; j++) upk(v1[j], a[j], b[j]);
        float4* r = (float4*)(g_scratch + (size_t)pos[2] * 16);
        if (2 < ecnt) {
            __stcs(r + 0, make_float4(a[0], a[1], a[2], a[3]));
            __stcs(r + 1, make_float4(a[4], a[5], a[6], a[7]));
            __stcs(r + 2, make_float4(a[8], a[9], a[10], a[11]));
            __stcs(r + 3, make_float4(a[12], a[13], a[14], 0.f));
        }
        r = (float4*)(g_scratch + (size_t)pos[3] * 16);
        if (3 < ecnt) {
            __stcs(r + 0, make_float4(b[0], b[1], b[2], b[3]));
            __stcs(r + 1, make_float4(b[4], b[5], b[6], b[7]));
            __stcs(r + 2, make_float4(b[8], b[9], b[10], b[11]));
            __stcs(r + 3, make_float4(b[12], b[13], b[14], 0.f));
        }
    }
}

// ---- stats kernel: one warp per node, coalesced streaming reads, 2-row ILP -----
__global__ __launch_bounds__(256) void stats_kernel(int n) {
    int warp = (blockIdx.x * blockDim.x + threadIdx.x) >> 5;
    if (warp >= n) return;
    int lane = threadIdx.x & 31;
    int j = lane & 15;
    int half = lane >> 4;

    int cnt = g_hist[warp];
    int base = g_start[warp];

    float s1 = 0.f, s2 = 0.f, s3 = 0.f, s4 = 0.f;
    float t1 = 0.f, t2 = 0.f, t3 = 0.f, t4 = 0.f;
    int i = half;
    for (; i + 2 < cnt; i += 4) {
        float v = __ldcs(g_scratch + (size_t)(base + i) * 16 + j);
        float w = __ldcs(g_scratch + (size_t)(base + i + 2) * 16 + j);
        float v2 = v * v, w2 = w * w;
        s1 += v;       t1 += w;
        s2 += v2;      t2 += w2;
        s3 += v2 * v;  t3 += w2 * w;
        s4 += v2 * v2; t4 += w2 * w2;
    }
    if (i < cnt) {
        float v = __ldcs(g_scratch + (size_t)(base + i) * 16 + j);
        float v2 = v * v;
        s1 += v; s2 += v2; s3 += v2 * v; s4 += v2 * v2;
    }
    s1 += t1; s2 += t2; s3 += t3; s4 += t4;

    s1 += __shfl_down_sync(0xffffffffu, s1, 16);
    s2 += __shfl_down_sync(0xffffffffu, s2, 16);
    s3 += __shfl_down_sync(0xffffffffu, s3, 16);
    s4 += __shfl_down_sync(0xffffffffu, s4, 16);

    if (lane < D1) {
        float denom = fmaxf((float)cnt, 1.f);
        float rin = 1.f / denom;
        float mu = s1 * rin, r2 = s2 * rin, r3 = s3 * rin, r4 = s4 * rin;
        float mu2 = mu * mu;
        float var = fmaxf(r2 - mu2, 0.f);
        float std_ = sqrtf(var + 1e-6f);
        float m3 = r3 - 3.f * mu * r2 + 2.f * mu * mu2;
        float m4 = r4 - 4.f * mu * r3 + 6.f * mu2 * r2 - 3.f * mu2 * mu2;
        float is = 1.f / std_;
        float is2 = is * is;
        ((float4*)g_stats)[(size_t)warp * 16 + lane] =
            make_float4(mu, std_, m3 * is2 * is, m4 * is2 * is2);
    }
}

// ---- node kernel: build 81-d feature, 81->10->10 MLP ---------------------------
__global__ __launch_bounds__(256) void node_kernel(
    const float* __restrict__ x_s,
    const float* __restrict__ u,
    const int* __restrict__ batch_s,
    const float* __restrict__ w1b, const float* __restrict__ b1b,
    const float* __restrict__ w2b, const float* __restrict__ b2b,
    float* __restrict__ out, int n)
{
    __shared__ float sw1[D2 * F_XS];
    __shared__ float sw2[F_XS * F_XS];
    __shared__ float sb1[F_XS];
    __shared__ float sb2[F_XS];
    for (int i = threadIdx.x; i < D2 * F_XS; i += blockDim.x) sw1[i] = w1b[i];
    for (int i = threadIdx.x; i < F_XS * F_XS; i += blockDim.x) sw2[i] = w2b[i];
    if (threadIdx.x < F_XS) {
        sb1[threadIdx.x] = b1b[threadIdx.x];
        sb2[threadIdx.x] = b2b[threadIdx.x];
    }
    __syncthreads();

    int nid = blockIdx.x * blockDim.x + threadIdx.x;
    if (nid >= n) return;

    float t[F_XS];
#pragma unroll
    for (int j = 0; j < F_XS; j++) t[j] = sb1[j];

#define ADD_FEAT(fv, i) do { \
        float _f = (fv); \
_Pragma("unroll") \
        for (int _j = 0; _j < F_XS; _j++) \
            t[_j] = fmaf(_f, sw1[(i) * F_XS + _j], t[_j]); \
    } while (0)

#pragma unroll
    for (int k = 0; k < F_XS; k++) ADD_FEAT(x_s[(size_t)nid * F_XS + k], k);

    ADD_FEAT((float)g_hist[nid], 10);

#pragma unroll
    for (int j = 0; j < D1; j++) {
        float4 st = ((const float4*)g_stats)[(size_t)nid * 16 + j];
        ADD_FEAT(st.x, 11 + j);
        ADD_FEAT(st.y, 26 + j);
        ADD_FEAT(st.z, 41 + j);
        ADD_FEAT(st.w, 56 + j);
    }

    int b = batch_s[nid];
#pragma unroll
    for (int k = 0; k < F_U; k++) ADD_FEAT(u[(size_t)b * F_U + k], 71 + k);
#undef ADD_FEAT

    float a[F_XS];
#pragma unroll
    for (int j = 0; j < F_XS; j++) a[j] = (t[j] > 0.f) ? t[j] : 0.1f * t[j];

#pragma unroll
    for (int j = 0; j < F_XS; j++) {
        float s = sb2[j];
#pragma unroll
        for (int i = 0; i < F_XS; i++) s = fmaf(a[i], sw2[i * F_XS + j], s);
        out[(size_t)nid * F_XS + j] = s;
    }
}

// ---------------------------------------------------------------------------
extern "C" void kernel_launch(void* const* d_in, const int* in_sizes, int n_in,
                              void* d_out, int out_size)
{
    const float* x_s       = (const float*)d_in[0];
    const float* x_t       = (const float*)d_in[1];
    const float* edge_attr = (const float*)d_in[2];
    const float* u         = (const float*)d_in[3];
    const int*   eidx      = (const int*)d_in[4];
    const int*   batch_s   = (const int*)d_in[5];
    const float* w1a = (const float*)d_in[6];
    const float* b1a = (const float*)d_in[7];
    const float* w2a = (const float*)d_in[8];
    const float* b2a = (const float*)d_in[9];
    const float* w1b = (const float*)d_in[10];
    const float* b1b = (const float*)d_in[11];
    const float* w2b = (const float*)d_in[12];
    const float* b2b = (const float*)d_in[13];

    int nS = in_sizes[0] / F_XS;     // 100000
    int E_ = in_sizes[2] / F_E;      // 4000000
    float* out = (float*)d_out;

    int nb = (nS + 1023) / 1024;     // scan blocks (<=128)

    zero_hist<<<(nS + 255) / 256, 256>>>(nS);
    hist_kernel<<<(E_ / 4 + 255) / 256 + 1, 256>>>(eidx, E_);
    scan1<<<nb, 1024>>>(nS);
    scan2<<<1, 128>>>(nb);
    scan3<<<nb, 1024>>>(nS);
    edge_kernel<<<(E_ + 511) / 512, 128>>>(x_t, edge_attr, eidx,
                                           w1a, b1a, w2a, b2a, E_);
    stats_kernel<<<(nS * 32 + 255) / 256, 256>>>(nS);
    node_kernel<<<(nS + 255) / 256, 256>>>(x_s, u, batch_s,
                                           w1b, b1b, w2b, b2b, out, nS);
}